// round 5
// baseline (speedup 1.0000x reference)
#include <cuda_runtime.h>
#include <cuda_bf16.h>
#include <math.h>
#include <stdint.h>

#define NTOK    8192
#define DIM     1024
#define HID     2048
#define NEXP    8

// ---------------- scratch (device globals; no allocation allowed) ----------
__device__ __nv_bfloat16 g_xh[(size_t)NTOK * DIM];           // x_norm hi
__device__ __nv_bfloat16 g_xl[(size_t)NTOK * DIM];           // x_norm lo
__device__ __nv_bfloat16 g_uwh[(size_t)NEXP * 4096 * 1024];  // up W^T hi, n' interleaved (a,g)
__device__ __nv_bfloat16 g_uwl[(size_t)NEXP * 4096 * 1024];  // up W^T lo
__device__ __nv_bfloat16 g_dwh[(size_t)NEXP * 1024 * 2048];  // down W^T hi [e][n][k]
__device__ __nv_bfloat16 g_dwl[(size_t)NEXP * 1024 * 2048];  // down W^T lo
__device__ __nv_bfloat16 g_uh[(size_t)NTOK * HID];           // swiglu hi
__device__ __nv_bfloat16 g_ul[(size_t)NTOK * HID];           // swiglu lo
__device__ int g_tokmap[NEXP * NTOK];
__device__ int g_count[NEXP];

// ---------------- helpers ----------------------------------------------
__device__ __forceinline__ uint32_t smem_u32(const void* p) {
    uint32_t a;
    asm("{ .reg .u64 t; cvta.to.shared.u64 t, %1; cvt.u32.u64 %0, t; }" : "=r"(a) : "l"(p));
    return a;
}
__device__ __forceinline__ void cp16(uint32_t dst, const void* src) {
    asm volatile("cp.async.cg.shared.global [%0], [%1], 16;" :: "r"(dst), "l"(src));
}
#define CP_COMMIT() asm volatile("cp.async.commit_group;")
#define SWZ64(o) ((o) ^ (((o) >> 3) & 0x30))

__device__ __forceinline__ void ldsm4(uint32_t* r, uint32_t addr) {
    asm volatile("ldmatrix.sync.aligned.m8n8.x4.shared.b16 {%0,%1,%2,%3}, [%4];"
        : "=r"(r[0]), "=r"(r[1]), "=r"(r[2]), "=r"(r[3]) : "r"(addr));
}
__device__ __forceinline__ void mma16816(float* c, const uint32_t* a, uint32_t b0, uint32_t b1) {
    asm volatile("mma.sync.aligned.m16n8k16.row.col.f32.bf16.bf16.f32 "
        "{%0,%1,%2,%3}, {%4,%5,%6,%7}, {%8,%9}, {%0,%1,%2,%3};"
        : "+f"(c[0]), "+f"(c[1]), "+f"(c[2]), "+f"(c[3])
        : "r"(a[0]), "r"(a[1]), "r"(a[2]), "r"(a[3]), "r"(b0), "r"(b1));
}
__device__ __forceinline__ uint32_t pack_bf(__nv_bfloat16 a, __nv_bfloat16 b) {
    return (uint32_t)__bfloat16_as_ushort(a) | ((uint32_t)__bfloat16_as_ushort(b) << 16);
}

// ---------------- smem layout for MMA kernels (BM=256, BN=128, BK=32) ------
#define OFF_AH   0
#define OFF_AL   16384
#define OFF_BH   32768
#define OFF_BL   40960
#define STAGE_SZ 49152
#define SM_TILES 1024
#define SMEM_MMA (1024 + 3*STAGE_SZ)   // 148480 B -> 1 CTA/SM, 512 threads

// ====================================================================
__global__ void zero_counts_kernel() {
    if (threadIdx.x < NEXP) g_count[threadIdx.x] = 0;
}

// ====================================================================
// Kernel 1: RMSNorm + routing; writes x_norm as bf16 hi/lo
// ====================================================================
__global__ __launch_bounds__(256)
void route_kernel(const float* __restrict__ x,
                  const float* __restrict__ scale,
                  const float* __restrict__ cent) {
    const int t = blockIdx.x, tid = threadIdx.x;
    const int lane = tid & 31, wid = tid >> 5;

    const float4 xv = ((const float4*)(x + (size_t)t * DIM))[tid];
    float ss = xv.x*xv.x + xv.y*xv.y + xv.z*xv.z + xv.w*xv.w;
    #pragma unroll
    for (int o = 16; o; o >>= 1) ss += __shfl_xor_sync(0xFFFFFFFFu, ss, o);
    __shared__ float swarp[8];
    if (lane == 0) swarp[wid] = ss;
    __syncthreads();
    float mean = 0.f;
    #pragma unroll
    for (int w = 0; w < 8; w++) mean += swarp[w];
    const float inv = rsqrtf(mean * (1.0f / DIM) + 1e-6f);

    const float4 sc = ((const float4*)scale)[tid];
    float v[4];
    v[0] = xv.x * (sc.x * inv); v[1] = xv.y * (sc.y * inv);
    v[2] = xv.z * (sc.z * inv); v[3] = xv.w * (sc.w * inv);

    uint32_t ph[2], pl[2];
    #pragma unroll
    for (int q = 0; q < 2; q++) {
        __nv_bfloat16 h0 = __float2bfloat16(v[2*q]);
        __nv_bfloat16 h1 = __float2bfloat16(v[2*q+1]);
        __nv_bfloat16 l0 = __float2bfloat16(v[2*q]   - __bfloat162float(h0));
        __nv_bfloat16 l1 = __float2bfloat16(v[2*q+1] - __bfloat162float(h1));
        ph[q] = pack_bf(h0, h1); pl[q] = pack_bf(l0, l1);
    }
    ((uint2*)(g_xh + (size_t)t * DIM))[tid] = make_uint2(ph[0], ph[1]);
    ((uint2*)(g_xl + (size_t)t * DIM))[tid] = make_uint2(pl[0], pl[1]);

    float p[NEXP];
    #pragma unroll
    for (int e = 0; e < NEXP; e++) {
        const float4 c = ((const float4*)(cent + (size_t)e * DIM))[tid];
        p[e] = (c.x*c.x - 2.f*v[0]*c.x) + (c.y*c.y - 2.f*v[1]*c.y)
             + (c.z*c.z - 2.f*v[2]*c.z) + (c.w*c.w - 2.f*v[3]*c.w);
    }
    __shared__ float sred[NEXP][8];
    #pragma unroll
    for (int e = 0; e < NEXP; e++) {
        float s = p[e];
        #pragma unroll
        for (int o = 16; o; o >>= 1) s += __shfl_xor_sync(0xFFFFFFFFu, s, o);
        if (lane == 0) sred[e][wid] = s;
    }
    __syncthreads();
    if (tid == 0) {
        int best = 0; float bd = 3.4e38f;
        #pragma unroll
        for (int e = 0; e < NEXP; e++) {
            float d = 0.f;
            #pragma unroll
            for (int w = 0; w < 8; w++) d += sred[e][w];
            if (d < bd) { bd = d; best = e; }
        }
        int pos = atomicAdd(&g_count[best], 1);
        g_tokmap[best * NTOK + pos] = t;
    }
}

// ====================================================================
// Kernel 2a/2b: weight convert + transpose (coalesced 4B writes)
// ====================================================================
__global__ __launch_bounds__(256)
void conv_up_kernel(const float* __restrict__ w) {   // [8][1024][4096]
    __shared__ float tile[32][65];
    const int e = blockIdx.z, n0 = blockIdx.x * 32, k0 = blockIdx.y * 64;
    const int tid = threadIdx.x;
    const float* W = w + ((size_t)e * 1024 + k0) * 4096 + n0;
    #pragma unroll
    for (int i = 0; i < 8; i++) {
        int idx = tid + i * 256;
        int kk = idx >> 5, nn = idx & 31;
        tile[nn][kk] = W[(size_t)kk * 4096 + nn];
    }
    __syncthreads();
    #pragma unroll
    for (int i = 0; i < 4; i++) {
        int idx = tid + i * 256;
        int nn = idx >> 5, kp = idx & 31;
        float v0 = tile[nn][2*kp], v1 = tile[nn][2*kp+1];
        __nv_bfloat16 h0 = __float2bfloat16(v0), h1 = __float2bfloat16(v1);
        __nv_bfloat16 l0 = __float2bfloat16(v0 - __bfloat162float(h0));
        __nv_bfloat16 l1 = __float2bfloat16(v1 - __bfloat162float(h1));
        int col = n0 + nn;
        int nprime = (col < 2048) ? (2 * col) : (2 * (col - 2048) + 1);
        size_t o32 = ((((size_t)e * 4096 + nprime) * 1024 + k0) >> 1) + kp;
        ((uint32_t*)g_uwh)[o32] = pack_bf(h0, h1);
        ((uint32_t*)g_uwl)[o32] = pack_bf(l0, l1);
    }
}

__global__ __launch_bounds__(256)
void conv_down_kernel(const float* __restrict__ w) { // [8][2048][1024] -> [e][n][k]
    __shared__ float tile[32][65];
    const int e = blockIdx.z, n0 = blockIdx.x * 32, k0 = blockIdx.y * 64;
    const int tid = threadIdx.x;
    const float* W = w + ((size_t)e * 2048 + k0) * 1024 + n0;
    #pragma unroll
    for (int i = 0; i < 8; i++) {
        int idx = tid + i * 256;
        int kk = idx >> 5, nn = idx & 31;
        tile[nn][kk] = W[(size_t)kk * 1024 + nn];
    }
    __syncthreads();
    #pragma unroll
    for (int i = 0; i < 4; i++) {
        int idx = tid + i * 256;
        int nn = idx >> 5, kp = idx & 31;
        float v0 = tile[nn][2*kp], v1 = tile[nn][2*kp+1];
        __nv_bfloat16 h0 = __float2bfloat16(v0), h1 = __float2bfloat16(v1);
        __nv_bfloat16 l0 = __float2bfloat16(v0 - __bfloat162float(h0));
        __nv_bfloat16 l1 = __float2bfloat16(v1 - __bfloat162float(h1));
        size_t o32 = ((((size_t)e * 1024 + n0 + nn) * 2048 + k0) >> 1) + kp;
        ((uint32_t*)g_dwh)[o32] = pack_bf(h0, h1);
        ((uint32_t*)g_dwl)[o32] = pack_bf(l0, l1);
    }
}

// ====================================================================
// Mainloop machinery: BM=256, BN=128, BK=32, 512 thr, 16 warps (4x4),
// warp tile 64x32.
// ====================================================================
__device__ __forceinline__ void load_chunk(uint32_t st, const int* rows_s, int tid,
                                           const __nv_bfloat16* Ah, const __nv_bfloat16* Al,
                                           const __nv_bfloat16* Bh, const __nv_bfloat16* Bl,
                                           int n0, int k0, int kstride) {
    #pragma unroll
    for (int i = 0; i < 2; i++) {
        int idx = tid + i * 512;                  // 1024 segs for A (hi & lo each)
        int r = idx >> 2, sg = idx & 3;
        uint32_t off = SWZ64((uint32_t)(r * 64 + sg * 16));
        size_t soA = (size_t)rows_s[r] * kstride + k0 + sg * 8;
        cp16(st + OFF_AH + off, Ah + soA);
        cp16(st + OFF_AL + off, Al + soA);
    }
    {
        int r = tid >> 2, sg = tid & 3;           // 512 segs for B (hi & lo each)
        uint32_t off = SWZ64((uint32_t)(r * 64 + sg * 16));
        size_t soB = (size_t)(n0 + r) * kstride + k0 + sg * 8;
        cp16(st + OFF_BH + off, Bh + soB);
        cp16(st + OFF_BL + off, Bl + soB);
    }
}

__device__ __forceinline__ void compute_chunk(uint32_t st, int lane, int mbase, int nbase,
                                              float acc[4][4][4]) {
    const int rsel = lane & 15;
    const int csel = lane >> 4;
    #pragma unroll
    for (int k16 = 0; k16 < 2; k16++) {
        const int cg = k16 * 2 + csel;
        uint32_t ah[4][4], al[4][4];
        #pragma unroll
        for (int mf = 0; mf < 4; mf++) {
            uint32_t boff = SWZ64((uint32_t)((mbase + mf*16 + rsel) * 64 + cg * 16));
            ldsm4(ah[mf], st + OFF_AH + boff);
            ldsm4(al[mf], st + OFF_AL + boff);
        }
        #pragma unroll
        for (int q = 0; q < 2; q++) {
            uint32_t bh[4], bl[4];
            uint32_t boff = SWZ64((uint32_t)((nbase + q*16 + rsel) * 64 + cg * 16));
            ldsm4(bh, st + OFF_BH + boff);
            ldsm4(bl, st + OFF_BL + boff);
            #pragma unroll
            for (int s = 0; s < 2; s++) {
                #pragma unroll
                for (int mf = 0; mf < 4; mf++) {
                    float* c = acc[mf][2*q + s];
                    mma16816(c, ah[mf], bh[s], bh[2 + s]);   // hh
                    mma16816(c, al[mf], bh[s], bh[2 + s]);   // lh
                    mma16816(c, ah[mf], bl[s], bl[2 + s]);   // hl
                }
            }
        }
    }
}

// ====================================================================
// Kernel 3: up GEMM + SwiGLU, BM=256
// ====================================================================
__global__ __launch_bounds__(512, 1)
void up_mma_kernel() {
    extern __shared__ char smem[];
    int* rows_s = (int*)smem;
    const uint32_t sb = smem_u32(smem);
    const int tid = threadIdx.x, lane = tid & 31, wid = tid >> 5;
    const int e = blockIdx.z;
    const int cnt = g_count[e];
    const int m0 = blockIdx.x * 256;
    if (m0 >= cnt) return;
    const int n0 = blockIdx.y * 128;     // n' base

    if (tid < 256) {
        int i = m0 + tid;
        rows_s[tid] = g_tokmap[e * NTOK + (i < cnt ? i : cnt - 1)];
    }
    __syncthreads();

    const __nv_bfloat16* Bh = g_uwh + (size_t)e * 4096 * 1024;
    const __nv_bfloat16* Bl = g_uwl + (size_t)e * 4096 * 1024;

    const int NC = 32;   // 1024 / 32
    load_chunk(sb + SM_TILES,            rows_s, tid, g_xh, g_xl, Bh, Bl, n0, 0,  DIM); CP_COMMIT();
    load_chunk(sb + SM_TILES + STAGE_SZ, rows_s, tid, g_xh, g_xl, Bh, Bl, n0, 32, DIM); CP_COMMIT();

    float acc[4][4][4];
    #pragma unroll
    for (int a = 0; a < 4; a++)
        #pragma unroll
        for (int b = 0; b < 4; b++)
            #pragma unroll
            for (int c = 0; c < 4; c++) acc[a][b][c] = 0.f;

    const int mbase = (wid & 3) * 64, nbase = (wid >> 2) * 32;

    #pragma unroll 1
    for (int c = 0; c < NC; c++) {
        if (c < NC - 1) asm volatile("cp.async.wait_group 1;" ::: "memory");
        else            asm volatile("cp.async.wait_group 0;" ::: "memory");
        __syncthreads();
        if (c + 2 < NC) {
            load_chunk(sb + SM_TILES + ((c+2)%3)*STAGE_SZ, rows_s, tid,
                       g_xh, g_xl, Bh, Bl, n0, (c+2)*32, DIM);
            CP_COMMIT();
        }
        compute_chunk(sb + SM_TILES + (c%3)*STAGE_SZ, lane, mbase, nbase, acc);
    }

    // Epilogue: per-thread SwiGLU -> smem staging -> coalesced 16B stores
    __syncthreads();
    __nv_bfloat16* sh_h = (__nv_bfloat16*)(smem + SM_TILES);
    __nv_bfloat16* sh_l = sh_h + 256 * 72;
    #pragma unroll
    for (int mf = 0; mf < 4; mf++) {
        #pragma unroll
        for (int nf = 0; nf < 4; nf++) {
            const float* c = acc[mf][nf];
            int jloc = (nbase >> 1) + nf * 4 + (lane & 3);
            #pragma unroll
            for (int r2 = 0; r2 < 2; r2++) {
                int mrow = mbase + mf*16 + (lane >> 2) + r2*8;
                float a = c[r2*2 + 0], g = c[r2*2 + 1];
                float y = a * g / (1.f + __expf(-g));
                __nv_bfloat16 h = __float2bfloat16(y);
                __nv_bfloat16 l = __float2bfloat16(y - __bfloat162float(h));
                sh_h[mrow * 72 + jloc] = h;
                sh_l[mrow * 72 + jloc] = l;
            }
        }
    }
    __syncthreads();
    const int j0 = blockIdx.y * 64;
    #pragma unroll
    for (int i = 0; i < 4; i++) {
        int idx = tid + i * 512;
        int r = idx >> 3, cb = idx & 7;
        if (m0 + r < cnt) {
            size_t o = (size_t)rows_s[r] * HID + j0 + cb * 8;
            *(uint4*)(g_uh + o) = *(const uint4*)(sh_h + r * 72 + cb * 8);
            *(uint4*)(g_ul + o) = *(const uint4*)(sh_l + r * 72 + cb * 8);
        }
    }
}

// ====================================================================
// Kernel 4: down GEMM + skip add + scatter, BM=256
// ====================================================================
__global__ __launch_bounds__(512, 1)
void down_mma_kernel(const float* __restrict__ x, float* __restrict__ out) {
    extern __shared__ char smem[];
    int* rows_s = (int*)smem;
    const uint32_t sb = smem_u32(smem);
    const int tid = threadIdx.x, lane = tid & 31, wid = tid >> 5;
    const int e = blockIdx.z;
    const int cnt = g_count[e];
    const int m0 = blockIdx.x * 256;
    if (m0 >= cnt) return;
    const int n0 = blockIdx.y * 128;

    if (tid < 256) {
        int i = m0 + tid;
        rows_s[tid] = g_tokmap[e * NTOK + (i < cnt ? i : cnt - 1)];
    }
    __syncthreads();

    const __nv_bfloat16* Bh = g_dwh + (size_t)e * 1024 * 2048;
    const __nv_bfloat16* Bl = g_dwl + (size_t)e * 1024 * 2048;

    const int NC = 64;   // 2048 / 32
    load_chunk(sb + SM_TILES,            rows_s, tid, g_uh, g_ul, Bh, Bl, n0, 0,  HID); CP_COMMIT();
    load_chunk(sb + SM_TILES + STAGE_SZ, rows_s, tid, g_uh, g_ul, Bh, Bl, n0, 32, HID); CP_COMMIT();

    float acc[4][4][4];
    #pragma unroll
    for (int a = 0; a < 4; a++)
        #pragma unroll
        for (int b = 0; b < 4; b++)
            #pragma unroll
            for (int c = 0; c < 4; c++) acc[a][b][c] = 0.f;

    const int mbase = (wid & 3) * 64, nbase = (wid >> 2) * 32;

    #pragma unroll 1
    for (int c = 0; c < NC; c++) {
        if (c < NC - 1) asm volatile("cp.async.wait_group 1;" ::: "memory");
        else            asm volatile("cp.async.wait_group 0;" ::: "memory");
        __syncthreads();
        if (c + 2 < NC) {
            load_chunk(sb + SM_TILES + ((c+2)%3)*STAGE_SZ, rows_s, tid,
                       g_uh, g_ul, Bh, Bl, n0, (c+2)*32, HID);
            CP_COMMIT();
        }
        compute_chunk(sb + SM_TILES + (c%3)*STAGE_SZ, lane, mbase, nbase, acc);
    }

    // Epilogue: stage fp32 results in smem, then coalesced skip-add + store
    __syncthreads();
    float* buf = (float*)(smem + SM_TILES);   // [256][132]
    #pragma unroll
    for (int mf = 0; mf < 4; mf++) {
        #pragma unroll
        for (int nf = 0; nf < 4; nf++) {
            const float* c = acc[mf][nf];
            int nloc = nbase + nf*8 + (lane & 3)*2;
            #pragma unroll
            for (int r2 = 0; r2 < 2; r2++) {
                int mrow = mbase + mf*16 + (lane >> 2) + r2*8;
                buf[mrow * 132 + nloc]     = c[r2*2 + 0];
                buf[mrow * 132 + nloc + 1] = c[r2*2 + 1];
            }
        }
    }
    __syncthreads();
    #pragma unroll
    for (int i = 0; i < 16; i++) {
        int idx = tid + i * 512;
        int r = idx >> 5, cb = idx & 31;
        if (m0 + r < cnt) {
            int token = rows_s[r];
            float4 v = *(const float4*)(buf + r * 132 + cb * 4);
            float4 s = *(const float4*)(x + (size_t)token * DIM + n0 + cb * 4);
            v.x += s.x; v.y += s.y; v.z += s.z; v.w += s.w;
            *(float4*)(out + (size_t)token * DIM + n0 + cb * 4) = v;
        }
    }
}

// ====================================================================
extern "C" void kernel_launch(void* const* d_in, const int* in_sizes, int n_in,
                              void* d_out, int out_size) {
    const float* x      = (const float*)d_in[0];   // [4,2048,1024]
    const float* scale  = (const float*)d_in[1];   // [1024]
    const float* cent   = (const float*)d_in[2];   // [8,1024]
    const float* up_w   = (const float*)d_in[3];   // [8,1024,4096]
    const float* down_w = (const float*)d_in[4];   // [8,2048,1024]
    float* out = (float*)d_out;                    // [4,2048,1024]

    cudaFuncSetAttribute(up_mma_kernel,   cudaFuncAttributeMaxDynamicSharedMemorySize, SMEM_MMA);
    cudaFuncSetAttribute(down_mma_kernel, cudaFuncAttributeMaxDynamicSharedMemorySize, SMEM_MMA);

    zero_counts_kernel<<<1, 32>>>();
    route_kernel<<<NTOK, 256>>>(x, scale, cent);
    conv_up_kernel<<<dim3(128, 16, NEXP), 256>>>(up_w);
    conv_down_kernel<<<dim3(32, 32, NEXP), 256>>>(down_w);
    up_mma_kernel<<<dim3(32, 32, NEXP), 512, SMEM_MMA>>>();
    down_mma_kernel<<<dim3(32, 8, NEXP), 512, SMEM_MMA>>>(x, out);
}

// round 6
// speedup vs baseline: 1.6227x; 1.6227x over previous
#include <cuda_runtime.h>
#include <cuda_bf16.h>
#include <math.h>
#include <stdint.h>

#define NTOK    8192
#define DIM     1024
#define HID     2048
#define NEXP    8

// ---------------- scratch (device globals; no allocation allowed) ----------
__device__ float g_xn[(size_t)NTOK * DIM];             // 32MB  x_norm (tf32-rounded fp32)
__device__ float g_uw[(size_t)NEXP * 4096 * 1024];     // 128MB up W^T, n' interleaved (a,g), tf32
__device__ float g_dw[(size_t)NEXP * 1024 * 2048];     // 64MB  down W^T [e][n][k], tf32
__device__ float g_u [(size_t)NTOK * HID];             // 64MB  swiglu out (tf32-rounded fp32)
__device__ int g_tokmap[NEXP * NTOK];
__device__ int g_count[NEXP];

// ---------------- helpers ----------------------------------------------
__device__ __forceinline__ uint32_t smem_u32(const void* p) {
    uint32_t a;
    asm("{ .reg .u64 t; cvta.to.shared.u64 t, %1; cvt.u32.u64 %0, t; }" : "=r"(a) : "l"(p));
    return a;
}
__device__ __forceinline__ void cp16(uint32_t dst, const void* src) {
    asm volatile("cp.async.cg.shared.global [%0], [%1], 16;" :: "r"(dst), "l"(src));
}
#define CP_COMMIT() asm volatile("cp.async.commit_group;")
#define SWZ128(o) ((o) ^ (((o) >> 3) & 0x70))

__device__ __forceinline__ float tf32r(float v) {
    uint32_t r;
    asm("cvt.rna.tf32.f32 %0, %1;" : "=r"(r) : "f"(v));
    return __uint_as_float(r);
}
__device__ __forceinline__ void ldsm4(uint32_t* r, uint32_t addr) {
    asm volatile("ldmatrix.sync.aligned.m8n8.x4.shared.b16 {%0,%1,%2,%3}, [%4];"
        : "=r"(r[0]), "=r"(r[1]), "=r"(r[2]), "=r"(r[3]) : "r"(addr));
}
__device__ __forceinline__ void mma1688(float* c, const uint32_t* a, uint32_t b0, uint32_t b1) {
    asm volatile("mma.sync.aligned.m16n8k8.row.col.f32.tf32.tf32.f32 "
        "{%0,%1,%2,%3}, {%4,%5,%6,%7}, {%8,%9}, {%0,%1,%2,%3};"
        : "+f"(c[0]), "+f"(c[1]), "+f"(c[2]), "+f"(c[3])
        : "r"(a[0]), "r"(a[1]), "r"(a[2]), "r"(a[3]), "r"(b0), "r"(b1));
}

// ---------------- smem layout (BM=128, BN=128, BK=32 fp32) -----------------
#define OFF_A    0
#define OFF_B    16384
#define STAGE_SZ 32768
#define SM_TILES 1024
#define SMEM_MMA (1024 + 3*STAGE_SZ)   // 99328 B -> 2 CTAs/SM

// ====================================================================
__global__ void zero_counts_kernel() {
    if (threadIdx.x < NEXP) g_count[threadIdx.x] = 0;
}

// ====================================================================
// Kernel 1: RMSNorm + routing; writes x_norm tf32-rounded fp32
// ====================================================================
__global__ __launch_bounds__(256)
void route_kernel(const float* __restrict__ x,
                  const float* __restrict__ scale,
                  const float* __restrict__ cent) {
    const int t = blockIdx.x, tid = threadIdx.x;
    const int lane = tid & 31, wid = tid >> 5;

    const float4 xv = ((const float4*)(x + (size_t)t * DIM))[tid];
    float ss = xv.x*xv.x + xv.y*xv.y + xv.z*xv.z + xv.w*xv.w;
    #pragma unroll
    for (int o = 16; o; o >>= 1) ss += __shfl_xor_sync(0xFFFFFFFFu, ss, o);
    __shared__ float swarp[8];
    if (lane == 0) swarp[wid] = ss;
    __syncthreads();
    float mean = 0.f;
    #pragma unroll
    for (int w = 0; w < 8; w++) mean += swarp[w];
    const float inv = rsqrtf(mean * (1.0f / DIM) + 1e-6f);

    const float4 sc = ((const float4*)scale)[tid];
    float v[4];
    v[0] = xv.x * (sc.x * inv); v[1] = xv.y * (sc.y * inv);
    v[2] = xv.z * (sc.z * inv); v[3] = xv.w * (sc.w * inv);

    float4 o4;
    o4.x = tf32r(v[0]); o4.y = tf32r(v[1]); o4.z = tf32r(v[2]); o4.w = tf32r(v[3]);
    ((float4*)(g_xn + (size_t)t * DIM))[tid] = o4;

    float p[NEXP];
    #pragma unroll
    for (int e = 0; e < NEXP; e++) {
        const float4 c = ((const float4*)(cent + (size_t)e * DIM))[tid];
        p[e] = (c.x*c.x - 2.f*v[0]*c.x) + (c.y*c.y - 2.f*v[1]*c.y)
             + (c.z*c.z - 2.f*v[2]*c.z) + (c.w*c.w - 2.f*v[3]*c.w);
    }
    __shared__ float sred[NEXP][8];
    #pragma unroll
    for (int e = 0; e < NEXP; e++) {
        float s = p[e];
        #pragma unroll
        for (int o = 16; o; o >>= 1) s += __shfl_xor_sync(0xFFFFFFFFu, s, o);
        if (lane == 0) sred[e][wid] = s;
    }
    __syncthreads();
    if (tid == 0) {
        int best = 0; float bd = 3.4e38f;
        #pragma unroll
        for (int e = 0; e < NEXP; e++) {
            float d = 0.f;
            #pragma unroll
            for (int w = 0; w < 8; w++) d += sred[e][w];
            if (d < bd) { bd = d; best = e; }
        }
        int pos = atomicAdd(&g_count[best], 1);
        g_tokmap[best * NTOK + pos] = t;
    }
}

// ====================================================================
// Kernel 2a: up weight transpose+interleave (a/g), tf32-round, fp32 out
// tile: 32 n x 64 k
// ====================================================================
__global__ __launch_bounds__(256)
void conv_up_kernel(const float* __restrict__ w) {   // [8][1024][4096]
    __shared__ float tile[32][65];
    const int e = blockIdx.z, n0 = blockIdx.x * 32, k0 = blockIdx.y * 64;
    const int tid = threadIdx.x;
    const float* W = w + ((size_t)e * 1024 + k0) * 4096 + n0;
    #pragma unroll
    for (int i = 0; i < 8; i++) {
        int idx = tid + i * 256;
        int kk = idx >> 5, nn = idx & 31;
        tile[nn][kk] = W[(size_t)kk * 4096 + nn];
    }
    __syncthreads();
    #pragma unroll
    for (int i = 0; i < 2; i++) {
        int idx = tid + i * 256;
        int nn = idx >> 4, q = idx & 15;
        int col = n0 + nn;
        int nprime = (col < 2048) ? (2 * col) : (2 * (col - 2048) + 1);
        float4 v;
        v.x = tf32r(tile[nn][q*4+0]);
        v.y = tf32r(tile[nn][q*4+1]);
        v.z = tf32r(tile[nn][q*4+2]);
        v.w = tf32r(tile[nn][q*4+3]);
        *(float4*)(g_uw + ((size_t)e * 4096 + nprime) * 1024 + k0 + q*4) = v;
    }
}

__global__ __launch_bounds__(256)
void conv_down_kernel(const float* __restrict__ w) { // [8][2048][1024] -> [e][n][k]
    __shared__ float tile[32][65];
    const int e = blockIdx.z, n0 = blockIdx.x * 32, k0 = blockIdx.y * 64;
    const int tid = threadIdx.x;
    const float* W = w + ((size_t)e * 2048 + k0) * 1024 + n0;
    #pragma unroll
    for (int i = 0; i < 8; i++) {
        int idx = tid + i * 256;
        int kk = idx >> 5, nn = idx & 31;
        tile[nn][kk] = W[(size_t)kk * 1024 + nn];
    }
    __syncthreads();
    #pragma unroll
    for (int i = 0; i < 2; i++) {
        int idx = tid + i * 256;
        int nn = idx >> 4, q = idx & 15;
        float4 v;
        v.x = tf32r(tile[nn][q*4+0]);
        v.y = tf32r(tile[nn][q*4+1]);
        v.z = tf32r(tile[nn][q*4+2]);
        v.w = tf32r(tile[nn][q*4+3]);
        *(float4*)(g_dw + ((size_t)e * 1024 + n0 + nn) * 2048 + k0 + q*4) = v;
    }
}

// ====================================================================
// Mainloop: BM=128, BN=128, BK=32 fp32, 256 thr, 8 warps (4x2), warp 32x64
// ====================================================================
__device__ __forceinline__ void load_chunk(uint32_t st, const int* rows_s, int tid,
                                           const float* A, const float* B,
                                           int n0, int k0, int kstride) {
    #pragma unroll
    for (int i = 0; i < 4; i++) {
        int idx = tid + i * 256;            // 1024 16B segs each for A and B
        int r = idx >> 3, sg = idx & 7;
        uint32_t off = SWZ128((uint32_t)(r * 128 + sg * 16));
        cp16(st + OFF_A + off, A + (size_t)rows_s[r] * kstride + k0 + sg * 4);
        cp16(st + OFF_B + off, B + (size_t)(n0 + r) * kstride + k0 + sg * 4);
    }
}

__device__ __forceinline__ void compute_chunk(uint32_t st, int lane, int mbase, int nbase,
                                              float acc[2][8][4]) {
    const int q = lane >> 3;       // ldmatrix address-provider group
    const int l7 = lane & 7;
    #pragma unroll
    for (int k8 = 0; k8 < 4; k8++) {
        uint32_t a[2][4];
        #pragma unroll
        for (int mf = 0; mf < 2; mf++) {
            // x4 blocks: q0: rows +0-7 segLo, q1: rows +8-15 segLo, q2: rows +0-7 segHi, q3: rows +8-15 segHi
            int rr = mbase + mf * 16 + (q & 1) * 8 + l7;
            int seg = k8 * 2 + (q >> 1);
            ldsm4(a[mf], st + OFF_A + SWZ128((uint32_t)(rr * 128 + seg * 16)));
        }
        #pragma unroll
        for (int bq = 0; bq < 4; bq++) {
            uint32_t b[4];
            // x4 blocks: q0: n rows +0-7 segLo (b0 lo-block), q1: +0-7 segHi (b1 lo),
            //            q2: +8-15 segLo (b0 hi-block), q3: +8-15 segHi (b1 hi)
            int rr = nbase + bq * 16 + (q >> 1) * 8 + l7;
            int seg = k8 * 2 + (q & 1);
            ldsm4(b, st + OFF_B + SWZ128((uint32_t)(rr * 128 + seg * 16)));
            #pragma unroll
            for (int h = 0; h < 2; h++) {
                #pragma unroll
                for (int mf = 0; mf < 2; mf++)
                    mma1688(acc[mf][bq * 2 + h], a[mf], b[2 * h], b[2 * h + 1]);
            }
        }
    }
}

// ====================================================================
// Kernel 3: up GEMM (tf32) + SwiGLU, smem-staged fp32 output
// ====================================================================
__global__ __launch_bounds__(256, 2)
void up_mma_kernel() {
    extern __shared__ char smem[];
    int* rows_s = (int*)smem;
    const uint32_t sb = smem_u32(smem);
    const int tid = threadIdx.x, lane = tid & 31, wid = tid >> 5;
    const int e = blockIdx.z;
    const int cnt = g_count[e];
    const int m0 = blockIdx.x * 128;
    if (m0 >= cnt) return;
    const int n0 = blockIdx.y * 128;     // n' base

    if (tid < 128) {
        int i = m0 + tid;
        rows_s[tid] = g_tokmap[e * NTOK + (i < cnt ? i : cnt - 1)];
    }
    __syncthreads();

    const float* B = g_uw + (size_t)e * 4096 * 1024;

    const int NC = 32;   // 1024 / 32
    load_chunk(sb + SM_TILES,            rows_s, tid, g_xn, B, n0, 0,  DIM); CP_COMMIT();
    load_chunk(sb + SM_TILES + STAGE_SZ, rows_s, tid, g_xn, B, n0, 32, DIM); CP_COMMIT();

    float acc[2][8][4];
    #pragma unroll
    for (int a = 0; a < 2; a++)
        #pragma unroll
        for (int b = 0; b < 8; b++)
            #pragma unroll
            for (int c = 0; c < 4; c++) acc[a][b][c] = 0.f;

    const int mbase = (wid & 3) * 32, nbase = (wid >> 2) * 64;

    #pragma unroll 1
    for (int c = 0; c < NC; c++) {
        if (c < NC - 1) asm volatile("cp.async.wait_group 1;" ::: "memory");
        else            asm volatile("cp.async.wait_group 0;" ::: "memory");
        __syncthreads();
        if (c + 2 < NC) {
            load_chunk(sb + SM_TILES + ((c+2)%3)*STAGE_SZ, rows_s, tid,
                       g_xn, B, n0, (c+2)*32, DIM);
            CP_COMMIT();
        }
        compute_chunk(sb + SM_TILES + (c%3)*STAGE_SZ, lane, mbase, nbase, acc);
    }

    // Epilogue: per-thread SwiGLU (even n'=a, odd n'=g) -> smem -> coalesced
    __syncthreads();
    float* buf = (float*)(smem + SM_TILES);    // [128][68]
    #pragma unroll
    for (int mf = 0; mf < 2; mf++) {
        #pragma unroll
        for (int nf = 0; nf < 8; nf++) {
            const float* c = acc[mf][nf];
            int jloc = (nbase >> 1) + nf * 4 + (lane & 3);
            #pragma unroll
            for (int r2 = 0; r2 < 2; r2++) {
                int mrow = mbase + mf*16 + (lane >> 2) + r2*8;
                float a = c[r2*2 + 0], g = c[r2*2 + 1];
                buf[mrow * 68 + jloc] = tf32r(a * g / (1.f + __expf(-g)));
            }
        }
    }
    __syncthreads();
    const int j0 = blockIdx.y * 64;
    #pragma unroll
    for (int i = 0; i < 8; i++) {
        int idx = tid + i * 256;
        int r = idx >> 4, c4 = idx & 15;
        if (m0 + r < cnt) {
            *(float4*)(g_u + (size_t)rows_s[r] * HID + j0 + c4 * 4) =
                *(const float4*)(buf + r * 68 + c4 * 4);
        }
    }
}

// ====================================================================
// Kernel 4: down GEMM (tf32) + skip add + scatter
// ====================================================================
__global__ __launch_bounds__(256, 2)
void down_mma_kernel(const float* __restrict__ x, float* __restrict__ out) {
    extern __shared__ char smem[];
    int* rows_s = (int*)smem;
    const uint32_t sb = smem_u32(smem);
    const int tid = threadIdx.x, lane = tid & 31, wid = tid >> 5;
    const int e = blockIdx.z;
    const int cnt = g_count[e];
    const int m0 = blockIdx.x * 128;
    if (m0 >= cnt) return;
    const int n0 = blockIdx.y * 128;

    if (tid < 128) {
        int i = m0 + tid;
        rows_s[tid] = g_tokmap[e * NTOK + (i < cnt ? i : cnt - 1)];
    }
    __syncthreads();

    const float* B = g_dw + (size_t)e * 1024 * 2048;

    const int NC = 64;   // 2048 / 32
    load_chunk(sb + SM_TILES,            rows_s, tid, g_u, B, n0, 0,  HID); CP_COMMIT();
    load_chunk(sb + SM_TILES + STAGE_SZ, rows_s, tid, g_u, B, n0, 32, HID); CP_COMMIT();

    float acc[2][8][4];
    #pragma unroll
    for (int a = 0; a < 2; a++)
        #pragma unroll
        for (int b = 0; b < 8; b++)
            #pragma unroll
            for (int c = 0; c < 4; c++) acc[a][b][c] = 0.f;

    const int mbase = (wid & 3) * 32, nbase = (wid >> 2) * 64;

    #pragma unroll 1
    for (int c = 0; c < NC; c++) {
        if (c < NC - 1) asm volatile("cp.async.wait_group 1;" ::: "memory");
        else            asm volatile("cp.async.wait_group 0;" ::: "memory");
        __syncthreads();
        if (c + 2 < NC) {
            load_chunk(sb + SM_TILES + ((c+2)%3)*STAGE_SZ, rows_s, tid,
                       g_u, B, n0, (c+2)*32, HID);
            CP_COMMIT();
        }
        compute_chunk(sb + SM_TILES + (c%3)*STAGE_SZ, lane, mbase, nbase, acc);
    }

    // Epilogue: stage fp32 in smem, then coalesced skip-add + store
    __syncthreads();
    float* buf = (float*)(smem + SM_TILES);   // [128][132]
    #pragma unroll
    for (int mf = 0; mf < 2; mf++) {
        #pragma unroll
        for (int nf = 0; nf < 8; nf++) {
            const float* c = acc[mf][nf];
            int nloc = nbase + nf*8 + (lane & 3)*2;
            #pragma unroll
            for (int r2 = 0; r2 < 2; r2++) {
                int mrow = mbase + mf*16 + (lane >> 2) + r2*8;
                buf[mrow * 132 + nloc]     = c[r2*2 + 0];
                buf[mrow * 132 + nloc + 1] = c[r2*2 + 1];
            }
        }
    }
    __syncthreads();
    #pragma unroll
    for (int i = 0; i < 16; i++) {
        int idx = tid + i * 256;
        int r = idx >> 5, cb = idx & 31;
        if (m0 + r < cnt) {
            int token = rows_s[r];
            float4 v = *(const float4*)(buf + r * 132 + cb * 4);
            float4 s = *(const float4*)(x + (size_t)token * DIM + n0 + cb * 4);
            v.x += s.x; v.y += s.y; v.z += s.z; v.w += s.w;
            *(float4*)(out + (size_t)token * DIM + n0 + cb * 4) = v;
        }
    }
}

// ====================================================================
extern "C" void kernel_launch(void* const* d_in, const int* in_sizes, int n_in,
                              void* d_out, int out_size) {
    const float* x      = (const float*)d_in[0];   // [4,2048,1024]
    const float* scale  = (const float*)d_in[1];   // [1024]
    const float* cent   = (const float*)d_in[2];   // [8,1024]
    const float* up_w   = (const float*)d_in[3];   // [8,1024,4096]
    const float* down_w = (const float*)d_in[4];   // [8,2048,1024]
    float* out = (float*)d_out;                    // [4,2048,1024]

    cudaFuncSetAttribute(up_mma_kernel,   cudaFuncAttributeMaxDynamicSharedMemorySize, SMEM_MMA);
    cudaFuncSetAttribute(down_mma_kernel, cudaFuncAttributeMaxDynamicSharedMemorySize, SMEM_MMA);

    zero_counts_kernel<<<1, 32>>>();
    route_kernel<<<NTOK, 256>>>(x, scale, cent);
    conv_up_kernel<<<dim3(128, 16, NEXP), 256>>>(up_w);
    conv_down_kernel<<<dim3(32, 32, NEXP), 256>>>(down_w);
    up_mma_kernel<<<dim3(64, 32, NEXP), 256, SMEM_MMA>>>();
    down_mma_kernel<<<dim3(64, 8, NEXP), 256, SMEM_MMA>>>(x, out);
}